// round 15
// baseline (speedup 1.0000x reference)
#include <cstdint>
#include <cuda_runtime.h>
#include <cuda_fp16.h>
#include <mma.h>

using namespace nvcuda;

#define N_EMBD 768
#define NHEAD  12
#define HS     64
#define TSEQ   1024
#define BATCH  8
#define MROWS  (BATCH*TSEQ)     /* 8192 */
#define FFDIM  (4*N_EMBD)       /* 3072 */
#define QKVD   (3*N_EMBD)       /* 2304 */
#define WINDOW 64

/* -------- scratch (no allocation allowed -> device globals) -------- */
__device__ float  g_x1  [MROWS*N_EMBD];
__device__ __half g_qkvh[MROWS*QKVD];
__device__ __half g_h1h [MROWS*N_EMBD];
__device__ __half g_atth[MROWS*N_EMBD];
__device__ __half g_h2h [MROWS*N_EMBD];
__device__ __half g_ffhh[MROWS*FFDIM];
/* converted half weights, ORIGINAL [K,N] layout */
__device__ __half g_wqkv[N_EMBD*QKVD];    /* fused q|k|v: [768][2304] */
__device__ __half g_wtp [N_EMBD*N_EMBD];
__device__ __half g_wt1 [N_EMBD*FFDIM];
__device__ __half g_wt2 [FFDIM*N_EMBD];

/* --------------------- cp.async helpers ---------------------------- */
__device__ __forceinline__ void cp_async16(uint32_t dst, const void* src)
{
    asm volatile("cp.async.cg.shared.global [%0], [%1], 16;\n" :: "r"(dst), "l"(src));
}
__device__ __forceinline__ void cp_async16z(uint32_t dst, const void* src, int src_sz)
{
    asm volatile("cp.async.cg.shared.global [%0], [%1], 16, %2;\n"
                 :: "r"(dst), "l"(src), "r"(src_sz));
}
__device__ __forceinline__ void cp_commit()
{
    asm volatile("cp.async.commit_group;\n");
}
__device__ __forceinline__ void cp_wait1()
{
    asm volatile("cp.async.wait_group 1;\n");
}
__device__ __forceinline__ void cp_wait0()
{
    asm volatile("cp.async.wait_group 0;\n");
}

__device__ __forceinline__ float gelu_tanh(float v)
{
    const float c = 0.7978845608028654f;
    return 0.5f * v * (1.f + tanhf(c * (v + 0.044715f * v * v * v)));
}

/* pack 4 floats -> 4 halfs (8B) */
__device__ __forceinline__ uint2 pack_h4(float a, float b, float c, float d)
{
    __half2 lo = __floats2half2_rn(a, b);
    __half2 hi = __floats2half2_rn(c, d);
    uint2 r;
    r.x = *(uint32_t*)&lo;
    r.y = *(uint32_t*)&hi;
    return r;
}

/* ------------- fused prep: convert weights + rmsnorm1 + tail ------- */
#define CONV_BLOCKS 6912
#define PREP_BLOCKS (CONV_BLOCKS + MROWS/8 + 1)

__global__ __launch_bounds__(256)
void prep_kernel(const float* wq, const float* wk, const float* wv,
                 const float* wp, const float* w1, const float* w2,
                 __half* whqkv, __half* whp, __half* wh1, __half* wh2,
                 const float* x, const float* g1, __half* h1h,
                 float* out, int tail_start, int out_size)
{
    const int bid = blockIdx.x;
    const int tid = threadIdx.x;

    if (bid < CONV_BLOCKS) {
        const float* src; __half* dst;
        int N, dstStride, dstOff, f4base;
        if (bid < 1728) {            /* 3 squares -> fused qkv buffer */
            int seg = bid / 576, r = bid % 576;
            src = (seg == 0) ? wq : (seg == 1) ? wk : wv;
            dst = whqkv; N = N_EMBD; dstStride = QKVD; dstOff = seg * N_EMBD;
            f4base = r * 256;
        } else if (bid < 2304) {
            src = wp; dst = whp; N = N_EMBD; dstStride = N_EMBD; dstOff = 0;
            f4base = (bid - 1728) * 256;
        } else if (bid < 4608) {
            src = w1; dst = wh1; N = FFDIM; dstStride = FFDIM; dstOff = 0;
            f4base = (bid - 2304) * 256;
        } else {
            src = w2; dst = wh2; N = N_EMBD; dstStride = N_EMBD; dstOff = 0;
            f4base = (bid - 4608) * 256;
        }
        int f4 = f4base + tid;
        int n4r = N >> 2;                    /* float4 per row */
        int k = f4 / n4r, n4 = f4 % n4r;
        float4 v = ((const float4*)src)[f4];
        *(uint2*)&dst[(size_t)k * dstStride + dstOff + n4 * 4] =
            pack_h4(v.x, v.y, v.z, v.w);
        return;
    }

    if (bid < CONV_BLOCKS + MROWS/8) {
        const int row  = (bid - CONV_BLOCKS) * 8 + (tid >> 5);
        const int lane = tid & 31;
        const float4* xr = (const float4*)(x + (size_t)row * N_EMBD);
        const float4* gr = (const float4*)g1;

        float4 v[6];
        float ss = 0.f;
        #pragma unroll
        for (int kk = 0; kk < 6; kk++) {
            v[kk] = xr[lane + 32 * kk];
            ss += v[kk].x*v[kk].x + v[kk].y*v[kk].y + v[kk].z*v[kk].z + v[kk].w*v[kk].w;
        }
        #pragma unroll
        for (int o = 16; o; o >>= 1) ss += __shfl_xor_sync(0xffffffffu, ss, o);
        const float r = rsqrtf(ss * (1.0f / N_EMBD) + 1e-6f);

        __half2* o2 = (__half2*)(h1h + (size_t)row * N_EMBD);
        #pragma unroll
        for (int kk = 0; kk < 6; kk++) {
            float4 gv = gr[lane + 32 * kk];
            int i = lane + 32 * kk;
            o2[i*2]   = __floats2half2_rn(v[kk].x * r * gv.x, v[kk].y * r * gv.y);
            o2[i*2+1] = __floats2half2_rn(v[kk].z * r * gv.z, v[kk].w * r * gv.w);
        }
        return;
    }

    /* tail zero (aux) */
    for (int i = tail_start + tid; i < out_size; i += 256)
        out[i] = 0.f;
}

/* ---------------- RMSNorm (standalone, for x1 -> h2) ---------------- */
__global__ __launch_bounds__(256)
void rmsnorm_h_kernel(const float* __restrict__ x,
                      const float* __restrict__ g,
                      __half* __restrict__ out)
{
    const int row  = blockIdx.x * 8 + (threadIdx.x >> 5);
    const int lane = threadIdx.x & 31;
    const float4* xr = (const float4*)(x + (size_t)row * N_EMBD);
    const float4* gr = (const float4*)g;

    float4 v[6];
    float ss = 0.f;
    #pragma unroll
    for (int k = 0; k < 6; k++) {
        v[k] = xr[lane + 32 * k];
        ss += v[k].x*v[k].x + v[k].y*v[k].y + v[k].z*v[k].z + v[k].w*v[k].w;
    }
    #pragma unroll
    for (int o = 16; o; o >>= 1) ss += __shfl_xor_sync(0xffffffffu, ss, o);
    const float r = rsqrtf(ss * (1.0f / N_EMBD) + 1e-6f);

    __half2* o2 = (__half2*)(out + (size_t)row * N_EMBD);
    #pragma unroll
    for (int k = 0; k < 6; k++) {
        float4 gv = gr[lane + 32 * k];
        int i = lane + 32 * k;
        o2[i*2]   = __floats2half2_rn(v[k].x * r * gv.x, v[k].y * r * gv.y);
        o2[i*2+1] = __floats2half2_rn(v[k].z * r * gv.z, v[k].w * r * gv.w);
    }
}

/* ------------------------- FP16 WMMA GEMM (BM=128) ----------------- */
/* C = A[M,K](row) @ W[K,N](row) ; A,W half, accum fp32                */
#define HSTR 72                        /* A-tile stride (64+8 halfs) */
#define BSTR 136                       /* B-tile stride (128+8 halfs) */
#define ATILE128_H (128 * HSTR)        /* 9216 halfs */
#define ATILE128_B (ATILE128_H * 2)    /* 18432 B */
#define BTILE_H (64 * BSTR)            /* 8704 halfs */
#define BTILE_B (BTILE_H * 2)          /* 17408 B */
#define SMEM_G128 (2*ATILE128_B + 2*BTILE_B)   /* 71680 B */
#define ESTR 136                       /* epilogue stage stride (floats) */

template<int MODE, int OUTH>
__global__ __launch_bounds__(256, 2)
void gemm_fp16(const __half* __restrict__ A, const __half* __restrict__ W,
               const float* __restrict__ bias, const float* __restrict__ resid,
               float* __restrict__ outf, __half* __restrict__ outh,
               int M, int N, int K)
{
    extern __shared__ __align__(16) unsigned char smem_raw[];
    __half* As = (__half*)smem_raw;                         /* [2][128][72] */
    __half* Bs = (__half*)(smem_raw + 2 * ATILE128_B);      /* [2][64][136] */
    const uint32_t asu = (uint32_t)__cvta_generic_to_shared(As);
    const uint32_t bsu = (uint32_t)__cvta_generic_to_shared(Bs);

    const int tid  = threadIdx.x;
    const int warp = tid >> 5;
    const int m0 = blockIdx.y * 128, n0 = blockIdx.x * 128;
    const int wm = (warp >> 2) * 64;
    const int wn = (warp & 3) * 32;

    wmma::fragment<wmma::accumulator, 16, 16, 16, float> acc[4][2];
    #pragma unroll
    for (int mi = 0; mi < 4; mi++)
        #pragma unroll
        for (int ni = 0; ni < 2; ni++)
            wmma::fill_fragment(acc[mi][ni], 0.f);

    const int nk = K >> 6;

    auto load_tile = [&](int ck, int s) {
        const __half* Ab = A + (size_t)m0 * K + ck * 64;
        const __half* Wb = W + (size_t)(ck * 64) * N + n0;
        #pragma unroll
        for (int i = 0; i < 4; i++) {
            int c = tid + i * 256;
            int r = c >> 3, col = (c & 7) * 8;
            cp_async16(asu + (uint32_t)(s * ATILE128_B + (r * HSTR + col) * 2),
                       Ab + (size_t)r * K + col);
        }
        #pragma unroll
        for (int i = 0; i < 4; i++) {
            int c = tid + i * 256;
            int r = c >> 4, col = (c & 15) * 8;
            cp_async16(bsu + (uint32_t)(s * BTILE_B + (r * BSTR + col) * 2),
                       Wb + (size_t)r * N + col);
        }
    };

    load_tile(0, 0); cp_commit();
    if (nk > 1) { load_tile(1, 1); cp_commit(); }

    for (int it = 0; it < nk; it++) {
        int s = it & 1;
        if (it + 1 < nk) cp_wait1(); else cp_wait0();
        __syncthreads();

        const __half* Acur = As + s * ATILE128_H;
        const __half* Bcur = Bs + s * BTILE_H;

        #pragma unroll
        for (int kk = 0; kk < 64; kk += 16) {
            wmma::fragment<wmma::matrix_a, 16, 16, 16, __half, wmma::row_major> af[4];
            wmma::fragment<wmma::matrix_b, 16, 16, 16, __half, wmma::row_major> bf[2];
            #pragma unroll
            for (int mi = 0; mi < 4; mi++)
                wmma::load_matrix_sync(af[mi], Acur + (wm + mi*16) * HSTR + kk, HSTR);
            #pragma unroll
            for (int ni = 0; ni < 2; ni++)
                wmma::load_matrix_sync(bf[ni], Bcur + kk * BSTR + wn + ni*16, BSTR);
            #pragma unroll
            for (int mi = 0; mi < 4; mi++)
                #pragma unroll
                for (int ni = 0; ni < 2; ni++)
                    wmma::mma_sync(acc[mi][ni], af[mi], bf[ni], acc[mi][ni]);
        }
        __syncthreads();
        if (it + 2 < nk) { load_tile(it + 2, s); cp_commit(); }
    }

    /* epilogue: stage whole 128x128 fp32 tile, then coalesced stores */
    float* stage = (float*)smem_raw;    /* 128 x ESTR = 69632 B */
    #pragma unroll
    for (int mi = 0; mi < 4; mi++)
        #pragma unroll
        for (int ni = 0; ni < 2; ni++)
            wmma::store_matrix_sync(stage + (wm + mi*16) * ESTR + wn + ni*16,
                                    acc[mi][ni], ESTR, wmma::mem_row_major);
    __syncthreads();

    #pragma unroll
    for (int i = 0; i < 16; i++) {
        int idx = tid + i * 256;
        int r = idx >> 5, c4 = idx & 31;
        int col = c4 * 4;
        float4 v = *(float4*)&stage[r * ESTR + col];
        int gr = m0 + r, gc = n0 + col;
        if (MODE >= 1) {
            float4 b = *(const float4*)&bias[gc];
            v.x += b.x; v.y += b.y; v.z += b.z; v.w += b.w;
        }
        if (MODE == 1) {
            float4 rr = *(const float4*)&resid[(size_t)gr * N + gc];
            v.x += rr.x; v.y += rr.y; v.z += rr.z; v.w += rr.w;
        }
        if (MODE == 2) {
            v.x = gelu_tanh(v.x); v.y = gelu_tanh(v.y);
            v.z = gelu_tanh(v.z); v.w = gelu_tanh(v.w);
        }
        if (OUTH)
            *(uint2*)&outh[(size_t)gr * N + gc] = pack_h4(v.x, v.y, v.z, v.w);
        else
            *(float4*)&outf[(size_t)gr * N + gc] = v;
    }
}

/* ------------------------- FP16 WMMA GEMM (BM=64) ------------------ */
#define ATILE64_H (64 * HSTR)          /* 4608 halfs */
#define ATILE64_B (ATILE64_H * 2)      /* 9216 B */
#define SMEM_G64  (2*ATILE64_B + 2*BTILE_B)  /* 53248 B */

template<int MODE, int OUTH>
__global__ __launch_bounds__(256, 4)
void gemm_fp16_s(const __half* __restrict__ A, const __half* __restrict__ W,
                 const float* __restrict__ bias, const float* __restrict__ resid,
                 float* __restrict__ outf, __half* __restrict__ outh,
                 int M, int N, int K)
{
    extern __shared__ __align__(16) unsigned char smem_raw[];
    __half* As = (__half*)smem_raw;                        /* [2][64][72]  */
    __half* Bs = (__half*)(smem_raw + 2 * ATILE64_B);      /* [2][64][136] */
    const uint32_t asu = (uint32_t)__cvta_generic_to_shared(As);
    const uint32_t bsu = (uint32_t)__cvta_generic_to_shared(Bs);

    const int tid  = threadIdx.x;
    const int warp = tid >> 5;
    const int m0 = blockIdx.y * 64, n0 = blockIdx.x * 128;
    const int wm = (warp >> 2) * 32;     /* 0 / 32  */
    const int wn = (warp & 3) * 32;      /* 0..96   */

    wmma::fragment<wmma::accumulator, 16, 16, 16, float> acc[2][2];
    #pragma unroll
    for (int mi = 0; mi < 2; mi++)
        #pragma unroll
        for (int ni = 0; ni < 2; ni++)
            wmma::fill_fragment(acc[mi][ni], 0.f);

    const int nk = K >> 6;

    auto load_tile = [&](int ck, int s) {
        const __half* Ab = A + (size_t)m0 * K + ck * 64;
        const __half* Wb = W + (size_t)(ck * 64) * N + n0;
        #pragma unroll
        for (int i = 0; i < 2; i++) {
            int c = tid + i * 256;
            int r = c >> 3, col = (c & 7) * 8;
            cp_async16(asu + (uint32_t)(s * ATILE64_B + (r * HSTR + col) * 2),
                       Ab + (size_t)r * K + col);
        }
        #pragma unroll
        for (int i = 0; i < 4; i++) {
            int c = tid + i * 256;
            int r = c >> 4, col = (c & 15) * 8;
            cp_async16(bsu + (uint32_t)(s * BTILE_B + (r * BSTR + col) * 2),
                       Wb + (size_t)r * N + col);
        }
    };

    load_tile(0, 0); cp_commit();
    if (nk > 1) { load_tile(1, 1); cp_commit(); }

    for (int it = 0; it < nk; it++) {
        int s = it & 1;
        if (it + 1 < nk) cp_wait1(); else cp_wait0();
        __syncthreads();

        const __half* Acur = As + s * ATILE64_H;
        const __half* Bcur = Bs + s * BTILE_H;

        #pragma unroll
        for (int kk = 0; kk < 64; kk += 16) {
            wmma::fragment<wmma::matrix_a, 16, 16, 16, __half, wmma::row_major> af[2];
            wmma::fragment<wmma::matrix_b, 16, 16, 16, __half, wmma::row_major> bf[2];
            #pragma unroll
            for (int mi = 0; mi < 2; mi++)
                wmma::load_matrix_sync(af[mi], Acur + (wm + mi*16) * HSTR + kk, HSTR);
            #pragma unroll
            for (int ni = 0; ni < 2; ni++)
                wmma::load_matrix_sync(bf[ni], Bcur + kk * BSTR + wn + ni*16, BSTR);
            #pragma unroll
            for (int mi = 0; mi < 2; mi++)
                #pragma unroll
                for (int ni = 0; ni < 2; ni++)
                    wmma::mma_sync(acc[mi][ni], af[mi], bf[ni], acc[mi][ni]);
        }
        __syncthreads();
        if (it + 2 < nk) { load_tile(it + 2, s); cp_commit(); }
    }

    /* epilogue: stage 64x128 fp32 tile, then coalesced stores */
    float* stage = (float*)smem_raw;    /* 64 x ESTR = 34816 B */
    #pragma unroll
    for (int mi = 0; mi < 2; mi++)
        #pragma unroll
        for (int ni = 0; ni < 2; ni++)
            wmma::store_matrix_sync(stage + (wm + mi*16) * ESTR + wn + ni*16,
                                    acc[mi][ni], ESTR, wmma::mem_row_major);
    __syncthreads();

    #pragma unroll
    for (int i = 0; i < 8; i++) {
        int idx = tid + i * 256;
        int r = idx >> 5, c4 = idx & 31;
        int col = c4 * 4;
        float4 v = *(float4*)&stage[r * ESTR + col];
        int gr = m0 + r, gc = n0 + col;
        if (MODE >= 1) {
            float4 b = *(const float4*)&bias[gc];
            v.x += b.x; v.y += b.y; v.z += b.z; v.w += b.w;
        }
        if (MODE == 1) {
            float4 rr = *(const float4*)&resid[(size_t)gr * N + gc];
            v.x += rr.x; v.y += rr.y; v.z += rr.z; v.w += rr.w;
        }
        if (MODE == 2) {
            v.x = gelu_tanh(v.x); v.y = gelu_tanh(v.y);
            v.z = gelu_tanh(v.z); v.w = gelu_tanh(v.w);
        }
        if (OUTH)
            *(uint2*)&outh[(size_t)gr * N + gc] = pack_h4(v.x, v.y, v.z, v.w);
        else
            *(float4*)&outf[(size_t)gr * N + gc] = v;
    }
}

/* ------------- tensor-core sliding-window (64) attention ----------- */
/* smem plan (53248 B, 4 CTA/SM):
   phase 1: Qs @ 0 (9216B) | Ks @ 9216 (18432B)
   S held in accumulator fragments across the phase sync.
   phase 2: Vs @ 0 (18432B) | Sf @ 18432 (64x136f, 34816B)
   Ph overlays Sf; O stage overlays Sf.                              */
#define AQ_OFF 0
#define AK_OFF 9216
#define AV_OFF 0
#define AS_OFF 18432
#define ATT_SMEM (AS_OFF + 64*136*4)   /* 53248 B */

__global__ __launch_bounds__(256, 4)
void attn_wmma(const __half* __restrict__ QKV, __half* __restrict__ O)
{
    extern __shared__ __align__(16) unsigned char smem[];
    __half* Qs = (__half*)(smem + AQ_OFF);   /* ld 72 */
    __half* Ks = (__half*)(smem + AK_OFF);   /* ld 72 */
    __half* Vs = (__half*)(smem + AV_OFF);   /* ld 72 (phase 2) */
    float*  Sf = (float*)(smem + AS_OFF);    /* ld 136 */
    __half* Ph = (__half*)(smem + AS_OFF);   /* ld 272 */
    const uint32_t squ = (uint32_t)__cvta_generic_to_shared(smem);

    const int tid = threadIdx.x, warp = tid >> 5, lane = tid & 31;
    const int b = blockIdx.z, h = blockIdx.y;
    const int t0 = blockIdx.x * 64;
    const int hc = h * HS;

    /* ---- phase 1 loads: Q + K ---- */
    #pragma unroll
    for (int i = 0; i < 2; i++) {
        int c = tid + i * 256;
        int r = c >> 3, col = (c & 7) * 8;
        cp_async16(squ + AQ_OFF + (uint32_t)(r * 144 + col * 2),
                   QKV + ((size_t)(b * TSEQ + t0 + r)) * QKVD + hc + col);
    }
    #pragma unroll
    for (int i = 0; i < 4; i++) {
        int c = tid + i * 256;
        int r = c >> 3, col = (c & 7) * 8;
        int s = t0 - 63 + r;
        int ok = (s >= 0 && s < TSEQ) ? 16 : 0;
        int sc = s < 0 ? 0 : (s >= TSEQ ? TSEQ - 1 : s);
        cp_async16z(squ + AK_OFF + (uint32_t)(r * 144 + col * 2),
                    QKV + ((size_t)(b * TSEQ + sc)) * QKVD + N_EMBD + hc + col, ok);
    }
    cp_commit();
    cp_wait0();
    __syncthreads();

    /* ---- S = Q @ Kext^T, held in fragments ---- */
    const int mb = warp & 3;
    const int nb0s = (warp >> 2) * 4;
    wmma::fragment<wmma::accumulator, 16, 16, 16, float> sa[4];
    #pragma unroll
    for (int t = 0; t < 4; t++) wmma::fill_fragment(sa[t], 0.f);
    #pragma unroll
    for (int k = 0; k < 4; k++) {
        wmma::fragment<wmma::matrix_a, 16, 16, 16, __half, wmma::row_major> af;
        wmma::load_matrix_sync(af, Qs + mb * 16 * 72 + k * 16, 72);
        #pragma unroll
        for (int t = 0; t < 4; t++) {
            wmma::fragment<wmma::matrix_b, 16, 16, 16, __half, wmma::col_major> bf;
            wmma::load_matrix_sync(bf, Ks + (nb0s + t) * 16 * 72 + k * 16, 72);
            wmma::mma_sync(sa[t], af, bf, sa[t]);
        }
    }
    __syncthreads();   /* Q/K dead -> region reusable */

    /* ---- issue V loads into [0, 18432) ---- */
    #pragma unroll
    for (int i = 0; i < 4; i++) {
        int c = tid + i * 256;
        int r = c >> 3, col = (c & 7) * 8;
        int s = t0 - 63 + r;
        int ok = (s >= 0 && s < TSEQ) ? 16 : 0;
        int sc = s < 0 ? 0 : (s >= TSEQ ? TSEQ - 1 : s);
        cp_async16z(squ + AV_OFF + (uint32_t)(r * 144 + col * 2),
                    QKV + ((size_t)(b * TSEQ + sc)) * QKVD + 2*N_EMBD + hc + col, ok);
    }
    cp_commit();

    /* ---- store S fragments to Sf ---- */
    #pragma unroll
    for (int t = 0; t < 4; t++)
        wmma::store_matrix_sync(Sf + mb * 16 * 136 + (nb0s + t) * 16, sa[t],
                                136, wmma::mem_row_major);
    __syncthreads();

    /* ---- masked softmax while V streams in; P (half) in place ---- */
    {
        for (int r = warp * 8; r < warp * 8 + 8; r++) {
            float vals[4];
            #pragma unroll
            for (int q = 0; q < 4; q++) {
                int j = lane + q * 32;
                float v = Sf[r * 136 + j] * 0.125f;
                bool valid = (j >= r) && (j <= r + 63) && (t0 - 63 + j >= 0);
                vals[q] = valid ? v : -1e30f;
            }
            float mx = fmaxf(fmaxf(vals[0], vals[1]), fmaxf(vals[2], vals[3]));
            #pragma unroll
            for (int o = 16; o; o >>= 1) mx = fmaxf(mx, __shfl_xor_sync(0xffffffffu, mx, o));
            float e[4], sum = 0.f;
            #pragma unroll
            for (int q = 0; q < 4; q++) { e[q] = __expf(vals[q] - mx); sum += e[q]; }
            #pragma unroll
            for (int o = 16; o; o >>= 1) sum += __shfl_xor_sync(0xffffffffu, sum, o);
            float inv = 1.f / sum;
            #pragma unroll
            for (int q = 0; q < 4; q++)
                Ph[r * 272 + lane + q * 32] = __float2half(e[q] * inv);
        }
    }
    cp_wait0();        /* V resident */
    __syncthreads();   /* Ph visible */

    /* ---- O = P @ V ---- */
    {
        const int nb0 = (warp >> 2) * 2;
        wmma::fragment<wmma::accumulator, 16, 16, 16, float> oa[2];
        #pragma unroll
        for (int t = 0; t < 2; t++) wmma::fill_fragment(oa[t], 0.f);
        #pragma unroll
        for (int k = 0; k < 8; k++) {
            wmma::fragment<wmma::matrix_a, 16, 16, 16, __half, wmma::row_major> af;
            wmma::load_matrix_sync(af, Ph + mb * 16 * 272 + k * 16, 272);
            #pragma unroll
            for (int t = 0; t < 2; t++) {
                wmma::fragment<wmma::matrix_b, 16, 16, 16, __half, wmma::row_major> bf;
                wmma::load_matrix_sync(bf, Vs + k * 16 * 72 + (nb0 + t) * 16, 72);
                wmma::mma_sync(oa[t], af, bf, oa[t]);
            }
        }
        __syncthreads();
        float* OS = (float*)(smem + AS_OFF);   /* 64 x 72 fp32 stage */
        #pragma unroll
        for (int t = 0; t < 2; t++)
            wmma::store_matrix_sync(OS + (mb * 16) * 72 + (nb0 + t) * 16,
                                    oa[t], 72, wmma::mem_row_major);
        __syncthreads();
        #pragma unroll
        for (int i = 0; i < 4; i++) {
            int idx = tid + i * 256;
            int r = idx >> 4, c4 = idx & 15;
            int col = c4 * 4;
            float4 v = *(float4*)&OS[r * 72 + col];
            *(uint2*)&O[((size_t)(b * TSEQ + t0 + r)) * N_EMBD + hc + col] =
                pack_h4(v.x, v.y, v.z, v.w);
        }
    }
}

/* --------------------------- launcher ------------------------------ */
extern "C" void kernel_launch(void* const* d_in, const int* in_sizes, int n_in,
                              void* d_out, int out_size)
{
    const float* x      = (const float*)d_in[0];
    const float* w_q    = (const float*)d_in[1];
    const float* w_k    = (const float*)d_in[2];
    const float* w_v    = (const float*)d_in[3];
    const float* w_proj = (const float*)d_in[4];
    const float* b_proj = (const float*)d_in[5];
    const float* w_ff1  = (const float*)d_in[6];
    const float* b_ff1  = (const float*)d_in[7];
    const float* w_ff2  = (const float*)d_in[8];
    const float* b_ff2  = (const float*)d_in[9];
    const float* g1     = (const float*)d_in[10];
    const float* g2     = (const float*)d_in[11];
    float* out = (float*)d_out;

    float *x1;
    __half *qkvh, *h1h, *atth, *h2h, *ffhh, *wqkv, *wtp, *wt1, *wt2;
    { void* p;
      cudaGetSymbolAddress(&p, g_x1);   x1   = (float*)p;
      cudaGetSymbolAddress(&p, g_qkvh); qkvh = (__half*)p;
      cudaGetSymbolAddress(&p, g_h1h);  h1h  = (__half*)p;
      cudaGetSymbolAddress(&p, g_atth); atth = (__half*)p;
      cudaGetSymbolAddress(&p, g_h2h);  h2h  = (__half*)p;
      cudaGetSymbolAddress(&p, g_ffhh); ffhh = (__half*)p;
      cudaGetSymbolAddress(&p, g_wqkv); wqkv = (__half*)p;
      cudaGetSymbolAddress(&p, g_wtp);  wtp  = (__half*)p;
      cudaGetSymbolAddress(&p, g_wt1);  wt1  = (__half*)p;
      cudaGetSymbolAddress(&p, g_wt2);  wt2  = (__half*)p;
    }

    cudaFuncSetAttribute(attn_wmma,
                         cudaFuncAttributeMaxDynamicSharedMemorySize, ATT_SMEM);
    cudaFuncSetAttribute(gemm_fp16<0,1>,
                         cudaFuncAttributeMaxDynamicSharedMemorySize, SMEM_G128);
    cudaFuncSetAttribute(gemm_fp16_s<1,0>,
                         cudaFuncAttributeMaxDynamicSharedMemorySize, SMEM_G64);
    cudaFuncSetAttribute(gemm_fp16_s<2,1>,
                         cudaFuncAttributeMaxDynamicSharedMemorySize, SMEM_G64);

    /* 0. fused prep: weight convert + rmsnorm1 + tail zero */
    const int TOT = MROWS * N_EMBD;
    prep_kernel<<<PREP_BLOCKS, 256>>>(w_q, w_k, w_v, w_proj, w_ff1, w_ff2,
                                      wqkv, wtp, wt1, wt2,
                                      x, g1, h1h,
                                      out, TOT, out_size);

    /* 1. fused QKV GEMM -> half (BM=128) */
    dim3 gqkv(QKVD / 128, MROWS / 128);
    gemm_fp16<0,1><<<gqkv, 256, SMEM_G128>>>(h1h, wqkv, nullptr, nullptr,
                                             nullptr, qkvh, MROWS, QKVD, N_EMBD);

    /* 2. tensor-core sliding-window attention -> half */
    dim3 ga(TSEQ / 64, NHEAD, BATCH);
    attn_wmma<<<ga, 256, ATT_SMEM>>>(qkvh, atth);

    /* 3. proj: x1 = x + att @ w_proj + b_proj (BM=64) */
    dim3 gp(N_EMBD / 128, MROWS / 64);
    gemm_fp16_s<1,0><<<gp, 256, SMEM_G64>>>(atth, wtp, b_proj, x,
                                            x1, nullptr, MROWS, N_EMBD, N_EMBD);

    /* 4. rmsnorm(x1)*g2 -> half */
    rmsnorm_h_kernel<<<MROWS/8, 256>>>(x1, g2, h2h);

    /* 5. ff1: gelu(h2 @ w_ff1 + b_ff1) -> half (BM=64) */
    dim3 gff1(FFDIM / 128, MROWS / 64);
    gemm_fp16_s<2,1><<<gff1, 256, SMEM_G64>>>(h2h, wt1, b_ff1, nullptr,
                                              nullptr, ffhh, MROWS, FFDIM, N_EMBD);

    /* 6. ff2: out = x1 + ffh @ w_ff2 + b_ff2 (BM=64) */
    gemm_fp16_s<1,0><<<gp, 256, SMEM_G64>>>(ffhh, wt2, b_ff2, x1,
                                            out, nullptr, MROWS, N_EMBD, FFDIM);
}

// round 16
// speedup vs baseline: 1.0038x; 1.0038x over previous
#include <cstdint>
#include <cuda_runtime.h>
#include <cuda_fp16.h>
#include <mma.h>

using namespace nvcuda;

#define N_EMBD 768
#define NHEAD  12
#define HS     64
#define TSEQ   1024
#define BATCH  8
#define MROWS  (BATCH*TSEQ)     /* 8192 */
#define FFDIM  (4*N_EMBD)       /* 3072 */
#define QKVD   (3*N_EMBD)       /* 2304 */
#define WINDOW 64

/* -------- scratch (no allocation allowed -> device globals) -------- */
__device__ float  g_x1  [MROWS*N_EMBD];
__device__ __half g_qkvh[MROWS*QKVD];
__device__ __half g_h1h [MROWS*N_EMBD];
__device__ __half g_atth[MROWS*N_EMBD];
__device__ __half g_h2h [MROWS*N_EMBD];
__device__ __half g_ffhh[MROWS*FFDIM];
/* converted half weights, ORIGINAL [K,N] layout */
__device__ __half g_wqkv[N_EMBD*QKVD];    /* fused q|k|v: [768][2304] */
__device__ __half g_wtp [N_EMBD*N_EMBD];
__device__ __half g_wt1 [N_EMBD*FFDIM];
__device__ __half g_wt2 [FFDIM*N_EMBD];

/* --------------------- cp.async helpers ---------------------------- */
__device__ __forceinline__ void cp_async16(uint32_t dst, const void* src)
{
    asm volatile("cp.async.cg.shared.global [%0], [%1], 16;\n" :: "r"(dst), "l"(src));
}
__device__ __forceinline__ void cp_async16z(uint32_t dst, const void* src, int src_sz)
{
    asm volatile("cp.async.cg.shared.global [%0], [%1], 16, %2;\n"
                 :: "r"(dst), "l"(src), "r"(src_sz));
}
__device__ __forceinline__ void cp_commit()
{
    asm volatile("cp.async.commit_group;\n");
}
__device__ __forceinline__ void cp_wait1()
{
    asm volatile("cp.async.wait_group 1;\n");
}
__device__ __forceinline__ void cp_wait0()
{
    asm volatile("cp.async.wait_group 0;\n");
}

__device__ __forceinline__ float gelu_tanh(float v)
{
    const float c = 0.7978845608028654f;
    return 0.5f * v * (1.f + tanhf(c * (v + 0.044715f * v * v * v)));
}

/* pack 4 floats -> 4 halfs (8B) */
__device__ __forceinline__ uint2 pack_h4(float a, float b, float c, float d)
{
    __half2 lo = __floats2half2_rn(a, b);
    __half2 hi = __floats2half2_rn(c, d);
    uint2 r;
    r.x = *(uint32_t*)&lo;
    r.y = *(uint32_t*)&hi;
    return r;
}

/* ------------- fused prep: convert weights + rmsnorm1 + tail ------- */
#define CONV_BLOCKS 6912
#define PREP_BLOCKS (CONV_BLOCKS + MROWS/8 + 1)

__global__ __launch_bounds__(256)
void prep_kernel(const float* wq, const float* wk, const float* wv,
                 const float* wp, const float* w1, const float* w2,
                 __half* whqkv, __half* whp, __half* wh1, __half* wh2,
                 const float* x, const float* g1, __half* h1h,
                 float* out, int tail_start, int out_size)
{
    const int bid = blockIdx.x;
    const int tid = threadIdx.x;

    if (bid < CONV_BLOCKS) {
        const float* src; __half* dst;
        int N, dstStride, dstOff, f4base;
        if (bid < 1728) {            /* 3 squares -> fused qkv buffer */
            int seg = bid / 576, r = bid % 576;
            src = (seg == 0) ? wq : (seg == 1) ? wk : wv;
            dst = whqkv; N = N_EMBD; dstStride = QKVD; dstOff = seg * N_EMBD;
            f4base = r * 256;
        } else if (bid < 2304) {
            src = wp; dst = whp; N = N_EMBD; dstStride = N_EMBD; dstOff = 0;
            f4base = (bid - 1728) * 256;
        } else if (bid < 4608) {
            src = w1; dst = wh1; N = FFDIM; dstStride = FFDIM; dstOff = 0;
            f4base = (bid - 2304) * 256;
        } else {
            src = w2; dst = wh2; N = N_EMBD; dstStride = N_EMBD; dstOff = 0;
            f4base = (bid - 4608) * 256;
        }
        int f4 = f4base + tid;
        int n4r = N >> 2;                    /* float4 per row */
        int k = f4 / n4r, n4 = f4 % n4r;
        float4 v = ((const float4*)src)[f4];
        *(uint2*)&dst[(size_t)k * dstStride + dstOff + n4 * 4] =
            pack_h4(v.x, v.y, v.z, v.w);
        return;
    }

    if (bid < CONV_BLOCKS + MROWS/8) {
        const int row  = (bid - CONV_BLOCKS) * 8 + (tid >> 5);
        const int lane = tid & 31;
        const float4* xr = (const float4*)(x + (size_t)row * N_EMBD);
        const float4* gr = (const float4*)g1;

        float4 v[6];
        float ss = 0.f;
        #pragma unroll
        for (int kk = 0; kk < 6; kk++) {
            v[kk] = xr[lane + 32 * kk];
            ss += v[kk].x*v[kk].x + v[kk].y*v[kk].y + v[kk].z*v[kk].z + v[kk].w*v[kk].w;
        }
        #pragma unroll
        for (int o = 16; o; o >>= 1) ss += __shfl_xor_sync(0xffffffffu, ss, o);
        const float r = rsqrtf(ss * (1.0f / N_EMBD) + 1e-6f);

        __half2* o2 = (__half2*)(h1h + (size_t)row * N_EMBD);
        #pragma unroll
        for (int kk = 0; kk < 6; kk++) {
            float4 gv = gr[lane + 32 * kk];
            int i = lane + 32 * kk;
            o2[i*2]   = __floats2half2_rn(v[kk].x * r * gv.x, v[kk].y * r * gv.y);
            o2[i*2+1] = __floats2half2_rn(v[kk].z * r * gv.z, v[kk].w * r * gv.w);
        }
        return;
    }

    /* tail zero (aux) */
    for (int i = tail_start + tid; i < out_size; i += 256)
        out[i] = 0.f;
}

/* ---------------- RMSNorm (standalone, for x1 -> h2) ---------------- */
__global__ __launch_bounds__(256)
void rmsnorm_h_kernel(const float* __restrict__ x,
                      const float* __restrict__ g,
                      __half* __restrict__ out)
{
    const int row  = blockIdx.x * 8 + (threadIdx.x >> 5);
    const int lane = threadIdx.x & 31;
    const float4* xr = (const float4*)(x + (size_t)row * N_EMBD);
    const float4* gr = (const float4*)g;

    float4 v[6];
    float ss = 0.f;
    #pragma unroll
    for (int k = 0; k < 6; k++) {
        v[k] = xr[lane + 32 * k];
        ss += v[k].x*v[k].x + v[k].y*v[k].y + v[k].z*v[k].z + v[k].w*v[k].w;
    }
    #pragma unroll
    for (int o = 16; o; o >>= 1) ss += __shfl_xor_sync(0xffffffffu, ss, o);
    const float r = rsqrtf(ss * (1.0f / N_EMBD) + 1e-6f);

    __half2* o2 = (__half2*)(out + (size_t)row * N_EMBD);
    #pragma unroll
    for (int k = 0; k < 6; k++) {
        float4 gv = gr[lane + 32 * k];
        int i = lane + 32 * k;
        o2[i*2]   = __floats2half2_rn(v[k].x * r * gv.x, v[k].y * r * gv.y);
        o2[i*2+1] = __floats2half2_rn(v[k].z * r * gv.z, v[k].w * r * gv.w);
    }
}

/* ------------------------- FP16 WMMA GEMM (BM=128) ----------------- */
/* C = A[M,K](row) @ W[K,N](row) ; A,W half, accum fp32                */
#define HSTR 72                        /* A-tile stride (64+8 halfs) */
#define BSTR 136                       /* B-tile stride (128+8 halfs) */
#define ATILE128_H (128 * HSTR)        /* 9216 halfs */
#define ATILE128_B (ATILE128_H * 2)    /* 18432 B */
#define BTILE_H (64 * BSTR)            /* 8704 halfs */
#define BTILE_B (BTILE_H * 2)          /* 17408 B */
#define SMEM_G128 (2*ATILE128_B + 2*BTILE_B)   /* 71680 B */
#define ESTR 136                       /* epilogue stage stride (floats) */

template<int MODE, int OUTH>
__global__ __launch_bounds__(256, 2)
void gemm_fp16(const __half* __restrict__ A, const __half* __restrict__ W,
               const float* __restrict__ bias, const float* __restrict__ resid,
               float* __restrict__ outf, __half* __restrict__ outh,
               int M, int N, int K)
{
    extern __shared__ __align__(16) unsigned char smem_raw[];
    __half* As = (__half*)smem_raw;                         /* [2][128][72] */
    __half* Bs = (__half*)(smem_raw + 2 * ATILE128_B);      /* [2][64][136] */
    const uint32_t asu = (uint32_t)__cvta_generic_to_shared(As);
    const uint32_t bsu = (uint32_t)__cvta_generic_to_shared(Bs);

    const int tid  = threadIdx.x;
    const int warp = tid >> 5;
    const int m0 = blockIdx.y * 128, n0 = blockIdx.x * 128;
    const int wm = (warp >> 2) * 64;
    const int wn = (warp & 3) * 32;

    wmma::fragment<wmma::accumulator, 16, 16, 16, float> acc[4][2];
    #pragma unroll
    for (int mi = 0; mi < 4; mi++)
        #pragma unroll
        for (int ni = 0; ni < 2; ni++)
            wmma::fill_fragment(acc[mi][ni], 0.f);

    const int nk = K >> 6;

    auto load_tile = [&](int ck, int s) {
        const __half* Ab = A + (size_t)m0 * K + ck * 64;
        const __half* Wb = W + (size_t)(ck * 64) * N + n0;
        #pragma unroll
        for (int i = 0; i < 4; i++) {
            int c = tid + i * 256;
            int r = c >> 3, col = (c & 7) * 8;
            cp_async16(asu + (uint32_t)(s * ATILE128_B + (r * HSTR + col) * 2),
                       Ab + (size_t)r * K + col);
        }
        #pragma unroll
        for (int i = 0; i < 4; i++) {
            int c = tid + i * 256;
            int r = c >> 4, col = (c & 15) * 8;
            cp_async16(bsu + (uint32_t)(s * BTILE_B + (r * BSTR + col) * 2),
                       Wb + (size_t)r * N + col);
        }
    };

    load_tile(0, 0); cp_commit();
    if (nk > 1) { load_tile(1, 1); cp_commit(); }

    for (int it = 0; it < nk; it++) {
        int s = it & 1;
        if (it + 1 < nk) cp_wait1(); else cp_wait0();
        __syncthreads();

        const __half* Acur = As + s * ATILE128_H;
        const __half* Bcur = Bs + s * BTILE_H;

        #pragma unroll
        for (int kk = 0; kk < 64; kk += 16) {
            wmma::fragment<wmma::matrix_a, 16, 16, 16, __half, wmma::row_major> af[4];
            wmma::fragment<wmma::matrix_b, 16, 16, 16, __half, wmma::row_major> bf[2];
            #pragma unroll
            for (int mi = 0; mi < 4; mi++)
                wmma::load_matrix_sync(af[mi], Acur + (wm + mi*16) * HSTR + kk, HSTR);
            #pragma unroll
            for (int ni = 0; ni < 2; ni++)
                wmma::load_matrix_sync(bf[ni], Bcur + kk * BSTR + wn + ni*16, BSTR);
            #pragma unroll
            for (int mi = 0; mi < 4; mi++)
                #pragma unroll
                for (int ni = 0; ni < 2; ni++)
                    wmma::mma_sync(acc[mi][ni], af[mi], bf[ni], acc[mi][ni]);
        }
        __syncthreads();
        if (it + 2 < nk) { load_tile(it + 2, s); cp_commit(); }
    }

    /* epilogue: stage whole 128x128 fp32 tile, then coalesced stores */
    float* stage = (float*)smem_raw;    /* 128 x ESTR = 69632 B */
    #pragma unroll
    for (int mi = 0; mi < 4; mi++)
        #pragma unroll
        for (int ni = 0; ni < 2; ni++)
            wmma::store_matrix_sync(stage + (wm + mi*16) * ESTR + wn + ni*16,
                                    acc[mi][ni], ESTR, wmma::mem_row_major);
    __syncthreads();

    #pragma unroll
    for (int i = 0; i < 16; i++) {
        int idx = tid + i * 256;
        int r = idx >> 5, c4 = idx & 31;
        int col = c4 * 4;
        float4 v = *(float4*)&stage[r * ESTR + col];
        int gr = m0 + r, gc = n0 + col;
        if (MODE >= 1) {
            float4 b = *(const float4*)&bias[gc];
            v.x += b.x; v.y += b.y; v.z += b.z; v.w += b.w;
        }
        if (MODE == 1) {
            float4 rr = *(const float4*)&resid[(size_t)gr * N + gc];
            v.x += rr.x; v.y += rr.y; v.z += rr.z; v.w += rr.w;
        }
        if (MODE == 2) {
            v.x = gelu_tanh(v.x); v.y = gelu_tanh(v.y);
            v.z = gelu_tanh(v.z); v.w = gelu_tanh(v.w);
        }
        if (OUTH)
            *(uint2*)&outh[(size_t)gr * N + gc] = pack_h4(v.x, v.y, v.z, v.w);
        else
            *(float4*)&outf[(size_t)gr * N + gc] = v;
    }
}

/* ------------------------- FP16 WMMA GEMM (BM=64) ------------------ */
#define ATILE64_H (64 * HSTR)          /* 4608 halfs */
#define ATILE64_B (ATILE64_H * 2)      /* 9216 B */
#define SMEM_G64  (2*ATILE64_B + 2*BTILE_B)  /* 53248 B */

template<int MODE, int OUTH>
__global__ __launch_bounds__(256, 3)
void gemm_fp16_s(const __half* __restrict__ A, const __half* __restrict__ W,
                 const float* __restrict__ bias, const float* __restrict__ resid,
                 float* __restrict__ outf, __half* __restrict__ outh,
                 int M, int N, int K)
{
    extern __shared__ __align__(16) unsigned char smem_raw[];
    __half* As = (__half*)smem_raw;                        /* [2][64][72]  */
    __half* Bs = (__half*)(smem_raw + 2 * ATILE64_B);      /* [2][64][136] */
    const uint32_t asu = (uint32_t)__cvta_generic_to_shared(As);
    const uint32_t bsu = (uint32_t)__cvta_generic_to_shared(Bs);

    const int tid  = threadIdx.x;
    const int warp = tid >> 5;
    const int m0 = blockIdx.y * 64, n0 = blockIdx.x * 128;
    const int wm = (warp >> 2) * 32;     /* 0 / 32  */
    const int wn = (warp & 3) * 32;      /* 0..96   */

    wmma::fragment<wmma::accumulator, 16, 16, 16, float> acc[2][2];
    #pragma unroll
    for (int mi = 0; mi < 2; mi++)
        #pragma unroll
        for (int ni = 0; ni < 2; ni++)
            wmma::fill_fragment(acc[mi][ni], 0.f);

    const int nk = K >> 6;

    auto load_tile = [&](int ck, int s) {
        const __half* Ab = A + (size_t)m0 * K + ck * 64;
        const __half* Wb = W + (size_t)(ck * 64) * N + n0;
        #pragma unroll
        for (int i = 0; i < 2; i++) {
            int c = tid + i * 256;
            int r = c >> 3, col = (c & 7) * 8;
            cp_async16(asu + (uint32_t)(s * ATILE64_B + (r * HSTR + col) * 2),
                       Ab + (size_t)r * K + col);
        }
        #pragma unroll
        for (int i = 0; i < 4; i++) {
            int c = tid + i * 256;
            int r = c >> 4, col = (c & 15) * 8;
            cp_async16(bsu + (uint32_t)(s * BTILE_B + (r * BSTR + col) * 2),
                       Wb + (size_t)r * N + col);
        }
    };

    load_tile(0, 0); cp_commit();
    if (nk > 1) { load_tile(1, 1); cp_commit(); }

    for (int it = 0; it < nk; it++) {
        int s = it & 1;
        if (it + 1 < nk) cp_wait1(); else cp_wait0();
        __syncthreads();

        const __half* Acur = As + s * ATILE64_H;
        const __half* Bcur = Bs + s * BTILE_H;

        #pragma unroll
        for (int kk = 0; kk < 64; kk += 16) {
            wmma::fragment<wmma::matrix_a, 16, 16, 16, __half, wmma::row_major> af[2];
            wmma::fragment<wmma::matrix_b, 16, 16, 16, __half, wmma::row_major> bf[2];
            #pragma unroll
            for (int mi = 0; mi < 2; mi++)
                wmma::load_matrix_sync(af[mi], Acur + (wm + mi*16) * HSTR + kk, HSTR);
            #pragma unroll
            for (int ni = 0; ni < 2; ni++)
                wmma::load_matrix_sync(bf[ni], Bcur + kk * BSTR + wn + ni*16, BSTR);
            #pragma unroll
            for (int mi = 0; mi < 2; mi++)
                #pragma unroll
                for (int ni = 0; ni < 2; ni++)
                    wmma::mma_sync(acc[mi][ni], af[mi], bf[ni], acc[mi][ni]);
        }
        __syncthreads();
        if (it + 2 < nk) { load_tile(it + 2, s); cp_commit(); }
    }

    /* epilogue: stage 64x128 fp32 tile, then coalesced stores */
    float* stage = (float*)smem_raw;    /* 64 x ESTR = 34816 B */
    #pragma unroll
    for (int mi = 0; mi < 2; mi++)
        #pragma unroll
        for (int ni = 0; ni < 2; ni++)
            wmma::store_matrix_sync(stage + (wm + mi*16) * ESTR + wn + ni*16,
                                    acc[mi][ni], ESTR, wmma::mem_row_major);
    __syncthreads();

    #pragma unroll
    for (int i = 0; i < 8; i++) {
        int idx = tid + i * 256;
        int r = idx >> 5, c4 = idx & 31;
        int col = c4 * 4;
        float4 v = *(float4*)&stage[r * ESTR + col];
        int gr = m0 + r, gc = n0 + col;
        if (MODE >= 1) {
            float4 b = *(const float4*)&bias[gc];
            v.x += b.x; v.y += b.y; v.z += b.z; v.w += b.w;
        }
        if (MODE == 1) {
            float4 rr = *(const float4*)&resid[(size_t)gr * N + gc];
            v.x += rr.x; v.y += rr.y; v.z += rr.z; v.w += rr.w;
        }
        if (MODE == 2) {
            v.x = gelu_tanh(v.x); v.y = gelu_tanh(v.y);
            v.z = gelu_tanh(v.z); v.w = gelu_tanh(v.w);
        }
        if (OUTH)
            *(uint2*)&outh[(size_t)gr * N + gc] = pack_h4(v.x, v.y, v.z, v.w);
        else
            *(float4*)&outf[(size_t)gr * N + gc] = v;
    }
}

/* ------------- tensor-core sliding-window (64) attention ----------- */
/* smem plan (53248 B, 4 CTA/SM):
   phase 1: Qs @ 0 (9216B) | Ks @ 9216 (18432B)
   S held in accumulator fragments across the phase sync.
   phase 2: Vs @ 0 (18432B) | Sf @ 18432 (64x136f, 34816B)
   Ph overlays Sf; O stage overlays Sf.                              */
#define AQ_OFF 0
#define AK_OFF 9216
#define AV_OFF 0
#define AS_OFF 18432
#define ATT_SMEM (AS_OFF + 64*136*4)   /* 53248 B */

__global__ __launch_bounds__(256, 4)
void attn_wmma(const __half* __restrict__ QKV, __half* __restrict__ O)
{
    extern __shared__ __align__(16) unsigned char smem[];
    __half* Qs = (__half*)(smem + AQ_OFF);   /* ld 72 */
    __half* Ks = (__half*)(smem + AK_OFF);   /* ld 72 */
    __half* Vs = (__half*)(smem + AV_OFF);   /* ld 72 (phase 2) */
    float*  Sf = (float*)(smem + AS_OFF);    /* ld 136 */
    __half* Ph = (__half*)(smem + AS_OFF);   /* ld 272 */
    const uint32_t squ = (uint32_t)__cvta_generic_to_shared(smem);

    const int tid = threadIdx.x, warp = tid >> 5, lane = tid & 31;
    const int b = blockIdx.z, h = blockIdx.y;
    const int t0 = blockIdx.x * 64;
    const int hc = h * HS;

    /* ---- phase 1 loads: Q + K ---- */
    #pragma unroll
    for (int i = 0; i < 2; i++) {
        int c = tid + i * 256;
        int r = c >> 3, col = (c & 7) * 8;
        cp_async16(squ + AQ_OFF + (uint32_t)(r * 144 + col * 2),
                   QKV + ((size_t)(b * TSEQ + t0 + r)) * QKVD + hc + col);
    }
    #pragma unroll
    for (int i = 0; i < 4; i++) {
        int c = tid + i * 256;
        int r = c >> 3, col = (c & 7) * 8;
        int s = t0 - 63 + r;
        int ok = (s >= 0 && s < TSEQ) ? 16 : 0;
        int sc = s < 0 ? 0 : (s >= TSEQ ? TSEQ - 1 : s);
        cp_async16z(squ + AK_OFF + (uint32_t)(r * 144 + col * 2),
                    QKV + ((size_t)(b * TSEQ + sc)) * QKVD + N_EMBD + hc + col, ok);
    }
    cp_commit();
    cp_wait0();
    __syncthreads();

    /* ---- S = Q @ Kext^T, held in fragments ---- */
    const int mb = warp & 3;
    const int nb0s = (warp >> 2) * 4;
    wmma::fragment<wmma::accumulator, 16, 16, 16, float> sa[4];
    #pragma unroll
    for (int t = 0; t < 4; t++) wmma::fill_fragment(sa[t], 0.f);
    #pragma unroll
    for (int k = 0; k < 4; k++) {
        wmma::fragment<wmma::matrix_a, 16, 16, 16, __half, wmma::row_major> af;
        wmma::load_matrix_sync(af, Qs + mb * 16 * 72 + k * 16, 72);
        #pragma unroll
        for (int t = 0; t < 4; t++) {
            wmma::fragment<wmma::matrix_b, 16, 16, 16, __half, wmma::col_major> bf;
            wmma::load_matrix_sync(bf, Ks + (nb0s + t) * 16 * 72 + k * 16, 72);
            wmma::mma_sync(sa[t], af, bf, sa[t]);
        }
    }
    __syncthreads();   /* Q/K dead -> region reusable */

    /* ---- issue V loads into [0, 18432) ---- */
    #pragma unroll
    for (int i = 0; i < 4; i++) {
        int c = tid + i * 256;
        int r = c >> 3, col = (c & 7) * 8;
        int s = t0 - 63 + r;
        int ok = (s >= 0 && s < TSEQ) ? 16 : 0;
        int sc = s < 0 ? 0 : (s >= TSEQ ? TSEQ - 1 : s);
        cp_async16z(squ + AV_OFF + (uint32_t)(r * 144 + col * 2),
                    QKV + ((size_t)(b * TSEQ + sc)) * QKVD + 2*N_EMBD + hc + col, ok);
    }
    cp_commit();

    /* ---- store S fragments to Sf ---- */
    #pragma unroll
    for (int t = 0; t < 4; t++)
        wmma::store_matrix_sync(Sf + mb * 16 * 136 + (nb0s + t) * 16, sa[t],
                                136, wmma::mem_row_major);
    __syncthreads();

    /* ---- masked softmax while V streams in; P (half) in place ---- */
    {
        for (int r = warp * 8; r < warp * 8 + 8; r++) {
            float vals[4];
            #pragma unroll
            for (int q = 0; q < 4; q++) {
                int j = lane + q * 32;
                float v = Sf[r * 136 + j] * 0.125f;
                bool valid = (j >= r) && (j <= r + 63) && (t0 - 63 + j >= 0);
                vals[q] = valid ? v : -1e30f;
            }
            float mx = fmaxf(fmaxf(vals[0], vals[1]), fmaxf(vals[2], vals[3]));
            #pragma unroll
            for (int o = 16; o; o >>= 1) mx = fmaxf(mx, __shfl_xor_sync(0xffffffffu, mx, o));
            float e[4], sum = 0.f;
            #pragma unroll
            for (int q = 0; q < 4; q++) { e[q] = __expf(vals[q] - mx); sum += e[q]; }
            #pragma unroll
            for (int o = 16; o; o >>= 1) sum += __shfl_xor_sync(0xffffffffu, sum, o);
            float inv = 1.f / sum;
            #pragma unroll
            for (int q = 0; q < 4; q++)
                Ph[r * 272 + lane + q * 32] = __float2half(e[q] * inv);
        }
    }
    cp_wait0();        /* V resident */
    __syncthreads();   /* Ph visible */

    /* ---- O = P @ V ---- */
    {
        const int nb0 = (warp >> 2) * 2;
        wmma::fragment<wmma::accumulator, 16, 16, 16, float> oa[2];
        #pragma unroll
        for (int t = 0; t < 2; t++) wmma::fill_fragment(oa[t], 0.f);
        #pragma unroll
        for (int k = 0; k < 8; k++) {
            wmma::fragment<wmma::matrix_a, 16, 16, 16, __half, wmma::row_major> af;
            wmma::load_matrix_sync(af, Ph + mb * 16 * 272 + k * 16, 272);
            #pragma unroll
            for (int t = 0; t < 2; t++) {
                wmma::fragment<wmma::matrix_b, 16, 16, 16, __half, wmma::row_major> bf;
                wmma::load_matrix_sync(bf, Vs + k * 16 * 72 + (nb0 + t) * 16, 72);
                wmma::mma_sync(oa[t], af, bf, oa[t]);
            }
        }
        __syncthreads();
        float* OS = (float*)(smem + AS_OFF);   /* 64 x 72 fp32 stage */
        #pragma unroll
        for (int t = 0; t < 2; t++)
            wmma::store_matrix_sync(OS + (mb * 16) * 72 + (nb0 + t) * 16,
                                    oa[t], 72, wmma::mem_row_major);
        __syncthreads();
        #pragma unroll
        for (int i = 0; i < 4; i++) {
            int idx = tid + i * 256;
            int r = idx >> 4, c4 = idx & 15;
            int col = c4 * 4;
            float4 v = *(float4*)&OS[r * 72 + col];
            *(uint2*)&O[((size_t)(b * TSEQ + t0 + r)) * N_EMBD + hc + col] =
                pack_h4(v.x, v.y, v.z, v.w);
        }
    }
}

/* --------------------------- launcher ------------------------------ */
extern "C" void kernel_launch(void* const* d_in, const int* in_sizes, int n_in,
                              void* d_out, int out_size)
{
    const float* x      = (const float*)d_in[0];
    const float* w_q    = (const float*)d_in[1];
    const float* w_k    = (const float*)d_in[2];
    const float* w_v    = (const float*)d_in[3];
    const float* w_proj = (const float*)d_in[4];
    const float* b_proj = (const float*)d_in[5];
    const float* w_ff1  = (const float*)d_in[6];
    const float* b_ff1  = (const float*)d_in[7];
    const float* w_ff2  = (const float*)d_in[8];
    const float* b_ff2  = (const float*)d_in[9];
    const float* g1     = (const float*)d_in[10];
    const float* g2     = (const float*)d_in[11];
    float* out = (float*)d_out;

    float *x1;
    __half *qkvh, *h1h, *atth, *h2h, *ffhh, *wqkv, *wtp, *wt1, *wt2;
    { void* p;
      cudaGetSymbolAddress(&p, g_x1);   x1   = (float*)p;
      cudaGetSymbolAddress(&p, g_qkvh); qkvh = (__half*)p;
      cudaGetSymbolAddress(&p, g_h1h);  h1h  = (__half*)p;
      cudaGetSymbolAddress(&p, g_atth); atth = (__half*)p;
      cudaGetSymbolAddress(&p, g_h2h);  h2h  = (__half*)p;
      cudaGetSymbolAddress(&p, g_ffhh); ffhh = (__half*)p;
      cudaGetSymbolAddress(&p, g_wqkv); wqkv = (__half*)p;
      cudaGetSymbolAddress(&p, g_wtp);  wtp  = (__half*)p;
      cudaGetSymbolAddress(&p, g_wt1);  wt1  = (__half*)p;
      cudaGetSymbolAddress(&p, g_wt2);  wt2  = (__half*)p;
    }

    cudaFuncSetAttribute(attn_wmma,
                         cudaFuncAttributeMaxDynamicSharedMemorySize, ATT_SMEM);
    cudaFuncSetAttribute(gemm_fp16<0,1>,
                         cudaFuncAttributeMaxDynamicSharedMemorySize, SMEM_G128);
    cudaFuncSetAttribute(gemm_fp16_s<1,0>,
                         cudaFuncAttributeMaxDynamicSharedMemorySize, SMEM_G64);
    cudaFuncSetAttribute(gemm_fp16_s<2,1>,
                         cudaFuncAttributeMaxDynamicSharedMemorySize, SMEM_G64);

    /* 0. fused prep: weight convert + rmsnorm1 + tail zero */
    const int TOT = MROWS * N_EMBD;
    prep_kernel<<<PREP_BLOCKS, 256>>>(w_q, w_k, w_v, w_proj, w_ff1, w_ff2,
                                      wqkv, wtp, wt1, wt2,
                                      x, g1, h1h,
                                      out, TOT, out_size);

    /* 1. fused QKV GEMM -> half (BM=128) */
    dim3 gqkv(QKVD / 128, MROWS / 128);
    gemm_fp16<0,1><<<gqkv, 256, SMEM_G128>>>(h1h, wqkv, nullptr, nullptr,
                                             nullptr, qkvh, MROWS, QKVD, N_EMBD);

    /* 2. tensor-core sliding-window attention -> half */
    dim3 ga(TSEQ / 64, NHEAD, BATCH);
    attn_wmma<<<ga, 256, ATT_SMEM>>>(qkvh, atth);

    /* 3. proj: x1 = x + att @ w_proj + b_proj (BM=64) */
    dim3 gp(N_EMBD / 128, MROWS / 64);
    gemm_fp16_s<1,0><<<gp, 256, SMEM_G64>>>(atth, wtp, b_proj, x,
                                            x1, nullptr, MROWS, N_EMBD, N_EMBD);

    /* 4. rmsnorm(x1)*g2 -> half */
    rmsnorm_h_kernel<<<MROWS/8, 256>>>(x1, g2, h2h);

    /* 5. ff1: gelu(h2 @ w_ff1 + b_ff1) -> half (BM=64) */
    dim3 gff1(FFDIM / 128, MROWS / 64);
    gemm_fp16_s<2,1><<<gff1, 256, SMEM_G64>>>(h2h, wt1, b_ff1, nullptr,
                                              nullptr, ffhh, MROWS, FFDIM, N_EMBD);

    /* 6. ff2: out = x1 + ffh @ w_ff2 + b_ff2 (BM=64) */
    gemm_fp16_s<1,0><<<gp, 256, SMEM_G64>>>(ffhh, wt2, b_ff2, x1,
                                            out, nullptr, MROWS, N_EMBD, FFDIM);
}